// round 8
// baseline (speedup 1.0000x reference)
#include <cuda_runtime.h>
#include <math.h>

#define NPTS   131072
#define BATCH  8
#define VIEWS  2
#define HH     1024
#define WW     1024
#define NPIX   (VIEWS * BATCH * HH * WW)   // 16777216
#define FUSED_ELEMS NPIX

#define CP_BLOCKS   4096                   // each thread copies 4 float4
#define CP_THREADS  (CP_BLOCKS * 256)      // 1048576
#define PT_BLOCKS   (NPTS / 256)           // 512

// ---------------- scratch (device globals only; no allocation allowed) ------
__device__ float        g_proj[BATCH * VIEWS][12];  // 3x4 projection per (b,v)
__device__ float        g_row2[BATCH * VIEWS][4];   // row 2 of extr_inv per (b,v)
__device__ unsigned int g_near[BATCH * VIEWS];
__device__ unsigned int g_far[BATCH * VIEWS];
__device__ int          g_has[BATCH];
__device__ float        g_val[NPTS * 2];
__device__ int          g_pix[NPTS * 2];
// Packed collision map: key = ((n+1)<<32) | float_bits(val). 0 == clean.
// Invariant: all-zero before every kernel_launch call (zero-init at load;
// scatter_final_k re-zeroes exactly the entries each call dirties).
__device__ unsigned long long g_packed[NPIX];       // 128 MB

// ---------------- K0: 4x4 inverses (fp64 GJ w/ pivoting), proj, init --------
__global__ void setup_k(const float* __restrict__ intr,
                        const float* __restrict__ extr)
{
    int i = threadIdx.x;
    if (i < BATCH) g_has[i] = 0;
    if (i < BATCH * VIEWS) { g_near[i] = 0x7f800000u; g_far[i] = 0u; }
    if (i >= BATCH * VIEWS) return;

    double a[4][8];
    for (int r = 0; r < 4; r++)
        for (int c = 0; c < 4; c++) {
            a[r][c]     = (double)extr[i * 16 + r * 4 + c];
            a[r][4 + c] = (r == c) ? 1.0 : 0.0;
        }
    for (int col = 0; col < 4; col++) {
        int piv = col; double best = fabs(a[col][col]);
        for (int r = col + 1; r < 4; r++)
            if (fabs(a[r][col]) > best) { best = fabs(a[r][col]); piv = r; }
        if (piv != col)
            for (int c = 0; c < 8; c++) { double t = a[col][c]; a[col][c] = a[piv][c]; a[piv][c] = t; }
        double d = a[col][col];
        for (int c = 0; c < 8; c++) a[col][c] /= d;
        for (int r = 0; r < 4; r++) {
            if (r == col) continue;
            double f = a[r][col];
            for (int c = 0; c < 8; c++) a[r][c] -= f * a[col][c];
        }
    }
    double K[3][3];
    for (int r = 0; r < 3; r++)
        for (int c = 0; c < 3; c++)
            K[r][c] = (double)intr[i * 9 + r * 3 + c];
    for (int c = 0; c < 3; c++) { K[0][c] *= (double)WW; K[1][c] *= (double)HH; }

    for (int r = 0; r < 3; r++)
        for (int c = 0; c < 4; c++) {
            double s = 0.0;
            for (int j = 0; j < 3; j++) s += K[r][j] * a[j][4 + c];
            g_proj[i][r * 4 + c] = (float)s;
        }
    for (int c = 0; c < 4; c++) g_row2[i][c] = (float)a[2][4 + c];
}

// ---------------- Jacobi rotation on 4x4 symmetric, fixed (P,Q) -------------
// EXACT arithmetic (IEEE div / sqrt) — fast intrinsics here compound over 48
// rotations through the squared-conditioning DLT and blew rel_err to 2.5e-3.
template <int P, int Q>
__device__ __forceinline__ void jrot(float M[4][4], float Vv[4][4])
{
    float apq = M[P][Q];
    if (fabsf(apq) < 1e-30f) return;
    float app = M[P][P], aqq = M[Q][Q];
    float tau = (aqq - app) / (2.0f * apq);
    float t = copysignf(1.0f, tau) / (fabsf(tau) + sqrtf(1.0f + tau * tau));
    float c = 1.0f / sqrtf(1.0f + t * t);
    float s = t * c;
    M[P][P] = app - t * apq;
    M[Q][Q] = aqq + t * apq;
    M[P][Q] = 0.0f; M[Q][P] = 0.0f;
#pragma unroll
    for (int k = 0; k < 4; k++) {
        if (k == P || k == Q) continue;
        float mkp = M[k][P], mkq = M[k][Q];
        float np = c * mkp - s * mkq;
        float nq = s * mkp + c * mkq;
        M[k][P] = np; M[P][k] = np;
        M[k][Q] = nq; M[Q][k] = nq;
    }
#pragma unroll
    for (int k = 0; k < 4; k++) {
        float vkp = Vv[k][P], vkq = Vv[k][Q];
        Vv[k][P] = c * vkp - s * vkq;
        Vv[k][Q] = s * vkp + c * vkq;
    }
}

// ---------------- K1 (fused): bulk copy + points + packed atomicMax ---------
// Blocks [0, CP_BLOCKS): float4 copy, 4 chunks/thread (long pole, starts first).
// Blocks [CP_BLOCKS, CP_BLOCKS+PT_BLOCKS): one point per thread; the random
// disps gather AND the collision atomicMax overlap the streaming copy.
__global__ void fused_k(const float* __restrict__ mk0,
                        const float* __restrict__ mk1,
                        const float* __restrict__ conf,
                        const int*   __restrict__ bids,
                        const float* __restrict__ disps,
                        float*       __restrict__ out)
{
    if (blockIdx.x < CP_BLOCKS) {
        const float4* in4  = (const float4*)disps;
        float4*       out4 = (float4*)out;
        int i = blockIdx.x * blockDim.x + threadIdx.x;
#pragma unroll
        for (int j = 0; j < 4; j++)
            out4[i + j * CP_THREADS] = in4[i + j * CP_THREADS];
        return;
    }

    // ---- point path ----
    int n = (blockIdx.x - CP_BLOCKS) * blockDim.x + threadIdx.x;

    int   b  = bids[n];
    float cf = conf[n];
    float2 p0 = reinterpret_cast<const float2*>(mk0)[n];
    float2 p1 = reinterpret_cast<const float2*>(mk1)[n];

    const float* P0 = g_proj[b * 2 + 0];
    const float* P1 = g_proj[b * 2 + 1];

    float A[4][4];
#pragma unroll
    for (int k = 0; k < 4; k++) {
        A[0][k] = (P0[8 + k] * p0.x - P0[0 + k]) * cf;
        A[1][k] = (P0[8 + k] * p0.y - P0[4 + k]) * cf;
        A[2][k] = (P1[8 + k] * p1.x - P1[0 + k]) * cf;
        A[3][k] = (P1[8 + k] * p1.y - P1[4 + k]) * cf;
    }

    float M[4][4];
#pragma unroll
    for (int i = 0; i < 4; i++)
#pragma unroll
        for (int j = i; j < 4; j++) {
            float s = A[0][i] * A[0][j];
            s = fmaf(A[1][i], A[1][j], s);
            s = fmaf(A[2][i], A[2][j], s);
            s = fmaf(A[3][i], A[3][j], s);
            M[i][j] = s; M[j][i] = s;
        }

    float Vv[4][4] = {{1,0,0,0},{0,1,0,0},{0,0,1,0},{0,0,0,1}};

#pragma unroll 1
    for (int sweep = 0; sweep < 8; sweep++) {
        jrot<0,1>(M, Vv); jrot<0,2>(M, Vv); jrot<0,3>(M, Vv);
        jrot<1,2>(M, Vv); jrot<1,3>(M, Vv); jrot<2,3>(M, Vv);
    }

    // min-eigenvalue column via static predicated selects (register-resident)
    float dm = M[0][0];
    float h0 = Vv[0][0], h1 = Vv[1][0], h2 = Vv[2][0], h3 = Vv[3][0];
#pragma unroll
    for (int j = 1; j < 4; j++) {
        bool lt = M[j][j] < dm;
        dm = lt ? M[j][j] : dm;
        h0 = lt ? Vv[0][j] : h0;
        h1 = lt ? Vv[1][j] : h1;
        h2 = lt ? Vv[2][j] : h2;
        h3 = lt ? Vv[3][j] : h3;
    }
    float px = h0 / h3, py = h1 / h3, pz = h2 / h3;

    const float* r20 = g_row2[b * 2 + 0];
    const float* r21 = g_row2[b * 2 + 1];
    float z0 = fmaf(r20[0], px, fmaf(r20[1], py, fmaf(r20[2], pz, r20[3])));
    float z1 = fmaf(r21[0], px, fmaf(r21[1], py, fmaf(r21[2], pz, r21[3])));

    bool valid = (z0 > 0.0f) && (z0 < 500.0f) && (z1 > 0.0f) && (z1 < 500.0f);
    if (valid) {
        atomicMin(&g_near[b * 2 + 0], __float_as_uint(z0));
        atomicMin(&g_near[b * 2 + 1], __float_as_uint(z1));
        atomicMax(&g_far [b * 2 + 0], __float_as_uint(z0));
        atomicMax(&g_far [b * 2 + 1], __float_as_uint(z1));
        g_has[b] = 1;
    }

#pragma unroll
    for (int v = 0; v < 2; v++) {
        float2 p = (v == 0) ? p0 : p1;
        float  z = (v == 0) ? z0 : z1;
        int x = min(max((int)p.x, 0), WW - 1);
        int y = min(max((int)p.y, 0), HH - 1);
        int pix = (((v * BATCH + b) * HH + y) << 10) + x;   // W = 1024
        float cost = __ldg(&disps[pix]);
        float val  = valid ? (0.5f * (1.0f / z) + 0.5f * cost) : cost;
        g_pix[n * 2 + v] = pix;
        // winner = max point index n; n unique per pixel (v is part of pix),
        // so max over keys is deterministic and carries the winner's val.
        unsigned long long key =
            ((unsigned long long)(unsigned)(n + 1) << 32) | __float_as_uint(val);
        atomicMax(&g_packed[pix], key);
    }
}

// ---------------- K2: scatter winners (+self-clean) + near/far/flag ---------
__global__ void scatter_final_k(float* __restrict__ out)
{
    int i = blockIdx.x * blockDim.x + threadIdx.x;
    if (i < NPTS * 2) {
        int pix = i >= 0 ? g_pix[i] : 0;
        unsigned long long w = g_packed[pix];
        unsigned int myid = (unsigned)(i >> 1) + 1u;
        if ((unsigned)(w >> 32) == myid) {
            out[pix] = __uint_as_float((unsigned)(w & 0xffffffffu));
            g_packed[pix] = 0ull;          // restore all-zero invariant
        }
        // losers racing with the winner's zero see either the max key or 0;
        // neither matches their id, so they never write — race-free.
    }
    if (blockIdx.x == 0 && threadIdx.x < BATCH * VIEWS) {
        int t = threadIdx.x;
        int has = g_has[t >> 1];
        out[FUSED_ELEMS +  0 + t] = has ? __uint_as_float(g_near[t]) : 0.0f;
        out[FUSED_ELEMS + 16 + t] = has ? __uint_as_float(g_far[t])  : 500.0f;
        out[FUSED_ELEMS + 32 + t] = has ? 1.0f : 0.0f;
    }
}

// ---------------- launch -----------------------------------------------------
extern "C" void kernel_launch(void* const* d_in, const int* in_sizes, int n_in,
                              void* d_out, int out_size)
{
    const float* mk0   = (const float*)d_in[0];
    const float* mk1   = (const float*)d_in[1];
    const float* conf  = (const float*)d_in[2];
    const int*   bids  = (const int*)  d_in[3];
    const float* intr  = (const float*)d_in[4];
    const float* extr  = (const float*)d_in[5];
    const float* disps = (const float*)d_in[6];
    float* out = (float*)d_out;

    setup_k        <<<1, 32>>>(intr, extr);
    fused_k        <<<CP_BLOCKS + PT_BLOCKS, 256>>>(mk0, mk1, conf, bids, disps, out);
    scatter_final_k<<<(NPTS * 2) / 256, 256>>>(out);
}

// round 9
// speedup vs baseline: 2.1210x; 2.1210x over previous
#include <cuda_runtime.h>
#include <math.h>

#define NPTS   131072
#define BATCH  8
#define VIEWS  2
#define HH     1024
#define WW     1024
#define NPIX   (VIEWS * BATCH * HH * WW)   // 16777216
#define FUSED_ELEMS NPIX

#define PT_BLOCKS   (NPTS / 256)           // 512
#define CP_BLOCKS   4096                   // each thread copies 4 float4
#define CP_THREADS  (CP_BLOCKS * 256)      // 1048576

// ---------------- scratch (device globals only; no allocation allowed) ------
// near/far/has statically initialized to their "reset" state; scatter_final_k
// restores that state after consuming them, so every graph replay sees it.
__device__ unsigned int g_near[BATCH * VIEWS] = {
    0x7f800000u,0x7f800000u,0x7f800000u,0x7f800000u,
    0x7f800000u,0x7f800000u,0x7f800000u,0x7f800000u,
    0x7f800000u,0x7f800000u,0x7f800000u,0x7f800000u,
    0x7f800000u,0x7f800000u,0x7f800000u,0x7f800000u};
__device__ unsigned int g_far[BATCH * VIEWS]  = {0};
__device__ int          g_has[BATCH]          = {0};
__device__ int          g_winner[NPIX];             // 64 MB collision-resolution map
__device__ float        g_val[NPTS * 2];
__device__ int          g_pix[NPTS * 2];

// ---------------- Jacobi rotation on 4x4 symmetric, fixed (P,Q) -------------
// EXACT arithmetic (IEEE div / sqrt) — fast intrinsics here compound over 48
// rotations through the squared-conditioning DLT and blew rel_err to 2.5e-3.
template <int P, int Q>
__device__ __forceinline__ void jrot(float M[4][4], float Vv[4][4])
{
    float apq = M[P][Q];
    if (fabsf(apq) < 1e-30f) return;
    float app = M[P][P], aqq = M[Q][Q];
    float tau = (aqq - app) / (2.0f * apq);
    float t = copysignf(1.0f, tau) / (fabsf(tau) + sqrtf(1.0f + tau * tau));
    float c = 1.0f / sqrtf(1.0f + t * t);
    float s = t * c;
    M[P][P] = app - t * apq;
    M[Q][Q] = aqq + t * apq;
    M[P][Q] = 0.0f; M[Q][P] = 0.0f;
#pragma unroll
    for (int k = 0; k < 4; k++) {
        if (k == P || k == Q) continue;
        float mkp = M[k][P], mkq = M[k][Q];
        float np = c * mkp - s * mkq;
        float nq = s * mkp + c * mkq;
        M[k][P] = np; M[P][k] = np;
        M[k][Q] = nq; M[Q][k] = nq;
    }
#pragma unroll
    for (int k = 0; k < 4; k++) {
        float vkp = Vv[k][P], vkq = Vv[k][Q];
        Vv[k][P] = c * vkp - s * vkq;
        Vv[k][Q] = s * vkp + c * vkq;
    }
}

// ---------------- K1 (fused): per-block setup + points + bulk copy ----------
// Blocks [0, PT_BLOCKS): threads 0-15 build all 16 projection matrices in SMEM
//   (closed-form rigid inverse, fp64), then one point per thread.
// Blocks [PT_BLOCKS, PT_BLOCKS+CP_BLOCKS): float4 copy, 4 chunks/thread.
// This removes the serialized 21.7us setup_k launch entirely.
__global__ void fused_k(const float* __restrict__ mk0,
                        const float* __restrict__ mk1,
                        const float* __restrict__ conf,
                        const int*   __restrict__ bids,
                        const float* __restrict__ intr,
                        const float* __restrict__ extr,
                        const float* __restrict__ disps,
                        float*       __restrict__ out)
{
    if (blockIdx.x >= PT_BLOCKS) {
        // ---- copy path ----
        const float4* in4  = (const float4*)disps;
        float4*       out4 = (float4*)out;
        int i = (blockIdx.x - PT_BLOCKS) * blockDim.x + threadIdx.x;
#pragma unroll
        for (int j = 0; j < 4; j++)
            out4[i + j * CP_THREADS] = in4[i + j * CP_THREADS];
        return;
    }

    // ---- per-block setup: 16 (b,v) projection matrices into SMEM ----
    __shared__ float s_proj[BATCH * VIEWS][12];
    __shared__ float s_row2[BATCH * VIEWS][4];
    if (threadIdx.x < BATCH * VIEWS) {
        int i = threadIdx.x;
        // extrinsics are rigid: E = [R t; 0 0 0 1]  =>  inv = [R^T, -R^T t; 0 1]
        double R[3][3], t[3];
        for (int r = 0; r < 3; r++) {
            for (int c = 0; c < 3; c++) R[r][c] = (double)extr[i * 16 + r * 4 + c];
            t[r] = (double)extr[i * 16 + r * 4 + 3];
        }
        double inv[3][4];
        for (int r = 0; r < 3; r++) {
            inv[r][0] = R[0][r]; inv[r][1] = R[1][r]; inv[r][2] = R[2][r];
            inv[r][3] = -(R[0][r] * t[0] + R[1][r] * t[1] + R[2][r] * t[2]);
        }
        double K[3][3];
        for (int r = 0; r < 3; r++)
            for (int c = 0; c < 3; c++)
                K[r][c] = (double)intr[i * 9 + r * 3 + c];
        for (int c = 0; c < 3; c++) { K[0][c] *= (double)WW; K[1][c] *= (double)HH; }
        for (int r = 0; r < 3; r++)
            for (int c = 0; c < 4; c++) {
                double s = K[r][0] * inv[0][c] + K[r][1] * inv[1][c] + K[r][2] * inv[2][c];
                s_proj[i][r * 4 + c] = (float)s;
            }
        for (int c = 0; c < 4; c++) s_row2[i][c] = (float)inv[2][c];
    }
    __syncthreads();

    // ---- point path ----
    int n = blockIdx.x * blockDim.x + threadIdx.x;

    int   b  = bids[n];
    float cf = conf[n];
    float2 p0 = reinterpret_cast<const float2*>(mk0)[n];
    float2 p1 = reinterpret_cast<const float2*>(mk1)[n];

    const float* P0 = s_proj[b * 2 + 0];
    const float* P1 = s_proj[b * 2 + 1];

    float A[4][4];
#pragma unroll
    for (int k = 0; k < 4; k++) {
        A[0][k] = (P0[8 + k] * p0.x - P0[0 + k]) * cf;
        A[1][k] = (P0[8 + k] * p0.y - P0[4 + k]) * cf;
        A[2][k] = (P1[8 + k] * p1.x - P1[0 + k]) * cf;
        A[3][k] = (P1[8 + k] * p1.y - P1[4 + k]) * cf;
    }

    float M[4][4];
#pragma unroll
    for (int i = 0; i < 4; i++)
#pragma unroll
        for (int j = i; j < 4; j++) {
            float s = A[0][i] * A[0][j];
            s = fmaf(A[1][i], A[1][j], s);
            s = fmaf(A[2][i], A[2][j], s);
            s = fmaf(A[3][i], A[3][j], s);
            M[i][j] = s; M[j][i] = s;
        }

    float Vv[4][4] = {{1,0,0,0},{0,1,0,0},{0,0,1,0},{0,0,0,1}};

#pragma unroll 1
    for (int sweep = 0; sweep < 8; sweep++) {
        jrot<0,1>(M, Vv); jrot<0,2>(M, Vv); jrot<0,3>(M, Vv);
        jrot<1,2>(M, Vv); jrot<1,3>(M, Vv); jrot<2,3>(M, Vv);
    }

    // min-eigenvalue column via static predicated selects (register-resident)
    float dm = M[0][0];
    float h0 = Vv[0][0], h1 = Vv[1][0], h2 = Vv[2][0], h3 = Vv[3][0];
#pragma unroll
    for (int j = 1; j < 4; j++) {
        bool lt = M[j][j] < dm;
        dm = lt ? M[j][j] : dm;
        h0 = lt ? Vv[0][j] : h0;
        h1 = lt ? Vv[1][j] : h1;
        h2 = lt ? Vv[2][j] : h2;
        h3 = lt ? Vv[3][j] : h3;
    }
    float px = h0 / h3, py = h1 / h3, pz = h2 / h3;

    const float* r20 = s_row2[b * 2 + 0];
    const float* r21 = s_row2[b * 2 + 1];
    float z0 = fmaf(r20[0], px, fmaf(r20[1], py, fmaf(r20[2], pz, r20[3])));
    float z1 = fmaf(r21[0], px, fmaf(r21[1], py, fmaf(r21[2], pz, r21[3])));

    bool valid = (z0 > 0.0f) && (z0 < 500.0f) && (z1 > 0.0f) && (z1 < 500.0f);
    if (valid) {
        atomicMin(&g_near[b * 2 + 0], __float_as_uint(z0));
        atomicMin(&g_near[b * 2 + 1], __float_as_uint(z1));
        atomicMax(&g_far [b * 2 + 0], __float_as_uint(z0));
        atomicMax(&g_far [b * 2 + 1], __float_as_uint(z1));
        g_has[b] = 1;
    }

#pragma unroll
    for (int v = 0; v < 2; v++) {
        float2 p = (v == 0) ? p0 : p1;
        float  z = (v == 0) ? z0 : z1;
        int x = min(max((int)p.x, 0), WW - 1);
        int y = min(max((int)p.y, 0), HH - 1);
        int pix = (((v * BATCH + b) * HH + y) << 10) + x;   // W = 1024
        float cost = __ldg(&disps[pix]);
        float val  = valid ? (0.5f * (1.0f / z) + 0.5f * cost) : cost;
        g_val[n * 2 + v] = val;
        g_pix[n * 2 + v] = pix;
        g_winner[pix]    = -1;   // clear only touched pixels
    }
}

// ---------------- K2: collision winner = max point index --------------------
__global__ void winner_k()
{
    int i = blockIdx.x * blockDim.x + threadIdx.x;
    if (i >= NPTS * 2) return;
    atomicMax(&g_winner[g_pix[i]], i >> 1);
}

// ---------------- K3: scatter winners + near/far/flag tail (+self-reset) ----
__global__ void scatter_final_k(float* __restrict__ out)
{
    int i = blockIdx.x * blockDim.x + threadIdx.x;
    if (i < NPTS * 2) {
        int pix = g_pix[i];
        if (g_winner[pix] == (i >> 1)) out[pix] = g_val[i];
    }
    if (blockIdx.x == 0 && threadIdx.x < BATCH * VIEWS) {
        int t = threadIdx.x;
        int has = g_has[t >> 1];
        out[FUSED_ELEMS +  0 + t] = has ? __uint_as_float(g_near[t]) : 0.0f;
        out[FUSED_ELEMS + 16 + t] = has ? __uint_as_float(g_far[t])  : 500.0f;
        out[FUSED_ELEMS + 32 + t] = has ? 1.0f : 0.0f;
        // restore reset-state invariant for the next graph replay.
        // warp-ordered: all 16 lanes executed the reads above before these writes.
        g_near[t] = 0x7f800000u;
        g_far[t]  = 0u;
        if (t < BATCH) g_has[t] = 0;
    }
}

// ---------------- launch -----------------------------------------------------
extern "C" void kernel_launch(void* const* d_in, const int* in_sizes, int n_in,
                              void* d_out, int out_size)
{
    const float* mk0   = (const float*)d_in[0];
    const float* mk1   = (const float*)d_in[1];
    const float* conf  = (const float*)d_in[2];
    const int*   bids  = (const int*)  d_in[3];
    const float* intr  = (const float*)d_in[4];
    const float* extr  = (const float*)d_in[5];
    const float* disps = (const float*)d_in[6];
    float* out = (float*)d_out;

    fused_k        <<<PT_BLOCKS + CP_BLOCKS, 256>>>(mk0, mk1, conf, bids, intr, extr, disps, out);
    winner_k       <<<(NPTS * 2) / 256, 256>>>();
    scatter_final_k<<<(NPTS * 2) / 256, 256>>>(out);
}